// round 1
// baseline (speedup 1.0000x reference)
#include <cuda_runtime.h>
#include <math.h>

// Problem constants
#define HH 128
#define WW 128
#define HW 16384        // 128*128
#define NB 4            // batch
#define NC 64           // in channels
#define NO 64           // out channels
#define NMC 192         // 3 masks * 64 channels
#define NIC2 256        // 4 dilations * 64

// Scratch (device globals: allocation-free per harness rules)
__device__ float g_xm[NB * NMC * HW];        // 50.3 MB: x * mask, fused (m,c) channels
__device__ float g_cat[NB * NIC2 * HW];      // 67.1 MB: concatenated branch outputs
__device__ float g_wbr[NB * NMC * 9 * 64];   // packed branch weights [b][mc][tap][o]
__device__ float g_wout[NIC2 * 9 * 64];      // packed fuse weights  [ic][tap][o]

// ---------------------------------------------------------------------------
// Weight prepack: branch weights kernel[b,m,o,c,kh,kw] -> [b][mc=m*64+c][tap][o]
//                 fuse weights conv_out_w[o,ic,kh,kw]  -> [ic][tap][o]
// ---------------------------------------------------------------------------
__global__ void prep_w_kernel(const float* __restrict__ kern,
                              const float* __restrict__ cow)
{
    int i = blockIdx.x * 256 + threadIdx.x;
    if (i < NB * NMC * 9 * 64) {
        int o   = i & 63;
        int rt  = i >> 6;        // r*9 + tap
        int tap = rt % 9;
        int r   = rt / 9;        // b*192 + mc
        int b   = r / NMC;
        int mc  = r - b * NMC;
        int m   = mc >> 6;
        int c   = mc & 63;
        g_wbr[i] = kern[(((b * 3 + m) * 64 + o) * 64 + c) * 9 + tap];
    }
    if (i < NIC2 * 9 * 64) {
        int o   = i & 63;
        int rt  = i >> 6;
        int tap = rt % 9;
        int ic  = rt / 9;
        g_wout[i] = cow[(o * NIC2 + ic) * 9 + tap];
    }
}

// ---------------------------------------------------------------------------
// Stage 1: mask conv (3x3, pad 1) + channel softmax over 3. One thread/pixel.
// ---------------------------------------------------------------------------
__global__ void mask_kernel(const float* __restrict__ x,
                            const float* __restrict__ mw,
                            const float* __restrict__ mb,
                            float* __restrict__ masks)
{
    __shared__ float s_mw[3 * 64 * 9];
    for (int i = threadIdx.x; i < 3 * 64 * 9; i += 256) s_mw[i] = mw[i];
    __syncthreads();

    int gid = blockIdx.x * 256 + threadIdx.x;   // < 65536
    int b   = gid >> 14;
    int pid = gid & (HW - 1);
    int h   = pid >> 7;
    int w   = pid & 127;

    float a0 = mb[0], a1 = mb[1], a2 = mb[2];
    const float* xb = x + b * NC * HW;
    for (int c = 0; c < NC; c++) {
        const float* xc = xb + c * HW;
        const float* wc = s_mw + c * 9;
        #pragma unroll
        for (int kh = 0; kh < 3; kh++) {
            int hh = h + kh - 1;
            if ((unsigned)hh >= 128u) continue;
            #pragma unroll
            for (int kw = 0; kw < 3; kw++) {
                int ww = w + kw - 1;
                if ((unsigned)ww >= 128u) continue;
                float v = xc[hh * 128 + ww];
                int t = kh * 3 + kw;
                a0 = fmaf(v, wc[t],            a0);
                a1 = fmaf(v, wc[64 * 9 + t],   a1);
                a2 = fmaf(v, wc[128 * 9 + t],  a2);
            }
        }
    }
    float mx = fmaxf(a0, fmaxf(a1, a2));
    float e0 = expf(a0 - mx), e1 = expf(a1 - mx), e2 = expf(a2 - mx);
    float inv = 1.f / (e0 + e1 + e2);
    masks[(b * 3 + 0) * HW + pid] = e0 * inv;
    masks[(b * 3 + 1) * HW + pid] = e1 * inv;
    masks[(b * 3 + 2) * HW + pid] = e2 * inv;
}

// ---------------------------------------------------------------------------
// Stage 2: xm[b][m*64+c][p] = x[b][c][p] * masks[b][m][p]
// ---------------------------------------------------------------------------
__global__ void xm_kernel(const float* __restrict__ x,
                          const float* __restrict__ masks)
{
    int i = blockIdx.x * 256 + threadIdx.x;     // < 4*192*16384
    int pid = i & (HW - 1);
    int r   = i >> 14;          // b*192 + mc
    int b   = r / NMC;
    int mc  = r - b * NMC;
    int m   = mc >> 6;
    int c   = mc & 63;
    g_xm[i] = x[(b * NC + c) * HW + pid] * masks[(b * 3 + m) * HW + pid];
}

// ---------------------------------------------------------------------------
// Core conv tile: block computes 64 out-ch x (2 rows x 128 cols).
// 256 threads, each thread 8 o x 8 px register tile. K loop over NIC channels,
// 3x3 taps at dilation d, padding d (same-size output).
// ---------------------------------------------------------------------------
template <int NIC>
__device__ __forceinline__ void conv_tile(const float* __restrict__ xin,   // [NIC][HW]
                                          const float* __restrict__ wsrc,  // [NIC][9][64]
                                          int d, int h0, float acc[8][8])
{
    __shared__ float Bs[6 * 144];
    __shared__ float Ws[576];

    const int tid = threadIdx.x;
    const int tp = tid & 31, to = tid >> 5;
    const int Win = 128 + 2 * d;

    int rows[6];
    rows[0] = h0 - d;     rows[1] = h0;     rows[2] = h0 + d;
    rows[3] = h0 + 1 - d; rows[4] = h0 + 1; rows[5] = h0 + 1 + d;

    // Precompute this thread's smem-fill slots (<=4)
    int loff[4], lsm[4];
    int lcnt = 0;
    for (int idx = tid; idx < 6 * Win; idx += 256) {
        int r  = idx / Win;
        int cc = idx - r * Win;
        int hin = rows[r], win = cc - d;
        lsm[lcnt]  = r * 144 + cc;
        loff[lcnt] = ((unsigned)hin < 128u && (unsigned)win < 128u)
                        ? (hin * 128 + win) : -1;
        lcnt++;
    }

    #pragma unroll
    for (int i = 0; i < 8; i++)
        #pragma unroll
        for (int j = 0; j < 8; j++) acc[i][j] = 0.f;

    for (int mc = 0; mc < NIC; mc++) {
        const float* xc = xin + mc * HW;
        for (int l = 0; l < lcnt; l++) {
            int off = loff[l];
            float v = 0.f;
            if (off >= 0) v = __ldg(xc + off);
            Bs[lsm[l]] = v;
        }
        if (tid < 144) {
            ((float4*)Ws)[tid] = ((const float4*)(wsrc + mc * 576))[tid];
        }
        __syncthreads();

        #pragma unroll
        for (int kh = 0; kh < 3; kh++) {
            #pragma unroll
            for (int kw = 0; kw < 3; kw++) {
                const int t = kh * 3 + kw;
                float4 w0 = *(const float4*)(Ws + t * 64 + to * 8);
                float4 w1 = *(const float4*)(Ws + t * 64 + to * 8 + 4);
                float wv[8] = {w0.x, w0.y, w0.z, w0.w, w1.x, w1.y, w1.z, w1.w};
                int cbase = tp + kw * d;
                float bv[8];
                #pragma unroll
                for (int j = 0; j < 4; j++) {
                    bv[j]     = Bs[kh * 144 + cbase + 32 * j];
                    bv[4 + j] = Bs[(3 + kh) * 144 + cbase + 32 * j];
                }
                #pragma unroll
                for (int i = 0; i < 8; i++)
                    #pragma unroll
                    for (int j = 0; j < 8; j++)
                        acc[i][j] = fmaf(wv[i], bv[j], acc[i][j]);
            }
        }
        __syncthreads();
    }
}

// ---------------------------------------------------------------------------
// Stage 3: per (b, dilation) dense conv Cin=192 -> Cout=64, write into g_cat
// ---------------------------------------------------------------------------
__global__ void __launch_bounds__(256, 2) branch_kernel()
{
    int blk = blockIdx.x;              // [0, 1024)
    int hp = blk & 63;
    int di = (blk >> 6) & 3;
    int b  = blk >> 8;
    int d  = 2 * di + 1;               // 1,3,5,7
    int h0 = hp * 2;

    float acc[8][8];
    conv_tile<NMC>(g_xm + b * NMC * HW, g_wbr + b * NMC * 576, d, h0, acc);

    int tp = threadIdx.x & 31, to = threadIdx.x >> 5;
    float* cb = g_cat + (b * NIC2 + di * 64) * HW;
    #pragma unroll
    for (int i = 0; i < 8; i++) {
        float* cbo = cb + (to * 8 + i) * HW;
        #pragma unroll
        for (int j = 0; j < 8; j++) {
            int w_ = tp + 32 * (j & 3);
            int h_ = h0 + (j >> 2);
            cbo[h_ * 128 + w_] = acc[i][j];
        }
    }
}

// ---------------------------------------------------------------------------
// Stage 4: fuse conv Cin=256 -> Cout=64 (dil 1) + bias + BN(eval) + ReLU
// ---------------------------------------------------------------------------
__global__ void __launch_bounds__(256, 2) out_kernel(const float* __restrict__ cob,
                                                     const float* __restrict__ gamma,
                                                     const float* __restrict__ beta,
                                                     const float* __restrict__ mean,
                                                     const float* __restrict__ var,
                                                     float* __restrict__ out)
{
    int blk = blockIdx.x;              // [0, 256)
    int hp = blk & 63;
    int b  = blk >> 6;
    int h0 = hp * 2;

    float acc[8][8];
    conv_tile<NIC2>(g_cat + b * NIC2 * HW, g_wout, 1, h0, acc);

    int tp = threadIdx.x & 31, to = threadIdx.x >> 5;
    #pragma unroll
    for (int i = 0; i < 8; i++) {
        int o = to * 8 + i;
        float inv  = gamma[o] * rsqrtf(var[o] + 1e-5f);
        float addv = beta[o] - mean[o] * inv;
        float bias = cob[o];
        float* po = out + (b * NO + o) * HW;
        #pragma unroll
        for (int j = 0; j < 8; j++) {
            int w_ = tp + 32 * (j & 3);
            int h_ = h0 + (j >> 2);
            float v = (acc[i][j] + bias) * inv + addv;
            po[h_ * 128 + w_] = fmaxf(v, 0.f);
        }
    }
}

// ---------------------------------------------------------------------------
extern "C" void kernel_launch(void* const* d_in, const int* in_sizes, int n_in,
                              void* d_out, int out_size)
{
    const float* x     = (const float*)d_in[0];
    const float* kern  = (const float*)d_in[1];
    const float* mw    = (const float*)d_in[2];
    const float* mb    = (const float*)d_in[3];
    const float* cow   = (const float*)d_in[4];
    const float* cob   = (const float*)d_in[5];
    const float* gamma = (const float*)d_in[6];
    const float* beta  = (const float*)d_in[7];
    const float* mean  = (const float*)d_in[8];
    const float* var   = (const float*)d_in[9];

    float* out   = (float*)d_out;
    float* masks = out + NB * NO * HW;   // tuple output: (out, masks)

    prep_w_kernel<<<1728, 256>>>(kern, cow);
    mask_kernel<<<NB * HW / 256, 256>>>(x, mw, mb, masks);
    xm_kernel<<<NB * NMC * HW / 256, 256>>>(x, masks);
    branch_kernel<<<NB * 4 * 64, 256>>>();
    out_kernel<<<NB * 64, 256>>>(cob, gamma, beta, mean, var, out);
}

// round 2
// speedup vs baseline: 1.0622x; 1.0622x over previous
#include <cuda_runtime.h>
#include <math.h>

// Problem constants
#define HH 128
#define WW 128
#define HW 16384        // 128*128
#define NB 4            // batch
#define NC 64           // in channels
#define NO 64           // out channels
#define NMC 192         // 3 masks * 64 channels
#define NIC2 256        // 4 dilations * 64

// Scratch (device globals: allocation-free per harness rules)
__device__ float g_xm[NB * NMC * HW];        // 50.3 MB: x * mask, fused (m,c) channels
__device__ float g_cat[NB * NIC2 * HW];      // 67.1 MB: concatenated branch outputs
__device__ float g_wbr[NB * NMC * 9 * 64];   // packed branch weights [b][mc][tap][o]
__device__ float g_wout[NIC2 * 9 * 64];      // packed fuse weights  [ic][tap][o]

// Packed dual-fp32 FMA (sm_103a FFMA2; ptxas never auto-fuses this)
#define FMA2(acc, a, b) \
    asm("fma.rn.f32x2 %0, %1, %2, %0;" : "+l"(acc) : "l"(a), "l"(b))

// ---------------------------------------------------------------------------
// Weight prepack: branch weights kernel[b,m,o,c,kh,kw] -> [b][mc=m*64+c][tap][o]
//                 fuse weights conv_out_w[o,ic,kh,kw]  -> [ic][tap][o]
// ---------------------------------------------------------------------------
__global__ void prep_w_kernel(const float* __restrict__ kern,
                              const float* __restrict__ cow)
{
    int i = blockIdx.x * 256 + threadIdx.x;
    if (i < NB * NMC * 9 * 64) {
        int o   = i & 63;
        int rt  = i >> 6;        // r*9 + tap
        int tap = rt % 9;
        int r   = rt / 9;        // b*192 + mc
        int b   = r / NMC;
        int mc  = r - b * NMC;
        int m   = mc >> 6;
        int c   = mc & 63;
        g_wbr[i] = kern[(((b * 3 + m) * 64 + o) * 64 + c) * 9 + tap];
    }
    if (i < NIC2 * 9 * 64) {
        int o   = i & 63;
        int rt  = i >> 6;
        int tap = rt % 9;
        int ic  = rt / 9;
        g_wout[i] = cow[(o * NIC2 + ic) * 9 + tap];
    }
}

// ---------------------------------------------------------------------------
// Stage 1: mask conv (3x3, pad 1) + channel softmax over 3. One thread/pixel.
// ---------------------------------------------------------------------------
__global__ void mask_kernel(const float* __restrict__ x,
                            const float* __restrict__ mw,
                            const float* __restrict__ mb,
                            float* __restrict__ masks)
{
    __shared__ float s_mw[3 * 64 * 9];
    for (int i = threadIdx.x; i < 3 * 64 * 9; i += 256) s_mw[i] = mw[i];
    __syncthreads();

    int gid = blockIdx.x * 256 + threadIdx.x;   // < 65536
    int b   = gid >> 14;
    int pid = gid & (HW - 1);
    int h   = pid >> 7;
    int w   = pid & 127;

    float a0 = mb[0], a1 = mb[1], a2 = mb[2];
    const float* xb = x + b * NC * HW;
    for (int c = 0; c < NC; c++) {
        const float* xc = xb + c * HW;
        const float* wc = s_mw + c * 9;
        #pragma unroll
        for (int kh = 0; kh < 3; kh++) {
            int hh = h + kh - 1;
            if ((unsigned)hh >= 128u) continue;
            #pragma unroll
            for (int kw = 0; kw < 3; kw++) {
                int ww = w + kw - 1;
                if ((unsigned)ww >= 128u) continue;
                float v = xc[hh * 128 + ww];
                int t = kh * 3 + kw;
                a0 = fmaf(v, wc[t],            a0);
                a1 = fmaf(v, wc[64 * 9 + t],   a1);
                a2 = fmaf(v, wc[128 * 9 + t],  a2);
            }
        }
    }
    float mx = fmaxf(a0, fmaxf(a1, a2));
    float e0 = expf(a0 - mx), e1 = expf(a1 - mx), e2 = expf(a2 - mx);
    float inv = 1.f / (e0 + e1 + e2);
    masks[(b * 3 + 0) * HW + pid] = e0 * inv;
    masks[(b * 3 + 1) * HW + pid] = e1 * inv;
    masks[(b * 3 + 2) * HW + pid] = e2 * inv;
}

// ---------------------------------------------------------------------------
// Stage 2: xm[b][m*64+c][p] = x[b][c][p] * masks[b][m][p]
// ---------------------------------------------------------------------------
__global__ void xm_kernel(const float* __restrict__ x,
                          const float* __restrict__ masks)
{
    int i = blockIdx.x * 256 + threadIdx.x;     // < 4*192*16384
    int pid = i & (HW - 1);
    int r   = i >> 14;          // b*192 + mc
    int b   = r / NMC;
    int mc  = r - b * NMC;
    int m   = mc >> 6;
    int c   = mc & 63;
    g_xm[i] = x[(b * NC + c) * HW + pid] * masks[(b * 3 + m) * HW + pid];
}

// ---------------------------------------------------------------------------
// Core conv tile: block computes 64 out-ch x (2 rows x 128 cols).
// 256 threads; each thread owns a (4 o-pairs x 8 px) register tile of packed
// f32x2 accumulators (pair = two adjacent output channels). B values are
// stored DUPLICATED in smem (float2(v,v)) so the packed B operand is a single
// aligned LDS.64; packed weight pairs are contiguous in the [tap][o] layout.
// Two input channels per barrier pair.
// ---------------------------------------------------------------------------
template <int NIC>
__device__ __forceinline__ void conv_tile2(const float* __restrict__ xin,   // [NIC][HW]
                                           const float* __restrict__ wsrc,  // [NIC][9][64]
                                           int d, int h0,
                                           unsigned long long acc[4][8])
{
    __shared__ float2 Bs[2][6 * 144];   // duplicated values
    __shared__ float  Ws[2][576];

    const int tid = threadIdx.x;
    const int tp = tid & 31, to = tid >> 5;
    const int Win = 128 + 2 * d;

    int rows[6];
    rows[0] = h0 - d;     rows[1] = h0;     rows[2] = h0 + d;
    rows[3] = h0 + 1 - d; rows[4] = h0 + 1; rows[5] = h0 + 1 + d;

    // Precompute this thread's smem-fill slots (<=4)
    int loff[4], lsm[4];
    int lcnt = 0;
    for (int idx = tid; idx < 6 * Win; idx += 256) {
        int r  = idx / Win;
        int cc = idx - r * Win;
        int hin = rows[r], win = cc - d;
        lsm[lcnt]  = r * 144 + cc;
        loff[lcnt] = ((unsigned)hin < 128u && (unsigned)win < 128u)
                        ? (hin * 128 + win) : -1;
        lcnt++;
    }

    #pragma unroll
    for (int p = 0; p < 4; p++)
        #pragma unroll
        for (int j = 0; j < 8; j++) acc[p][j] = 0ull;

    for (int mc0 = 0; mc0 < NIC; mc0 += 2) {
        #pragma unroll
        for (int s = 0; s < 2; s++) {
            const float* xc = xin + (mc0 + s) * HW;
            for (int l = 0; l < lcnt; l++) {
                int off = loff[l];
                float v = 0.f;
                if (off >= 0) v = __ldg(xc + off);
                Bs[s][lsm[l]] = make_float2(v, v);
            }
        }
        if (tid < 144) {
            ((float4*)Ws[0])[tid] = ((const float4*)(wsrc + mc0 * 576))[tid];
            ((float4*)Ws[1])[tid] = ((const float4*)(wsrc + (mc0 + 1) * 576))[tid];
        }
        __syncthreads();

        #pragma unroll
        for (int s = 0; s < 2; s++) {
            const float*  ws = Ws[s];
            const float2* bs = Bs[s];
            #pragma unroll
            for (int t = 0; t < 9; t++) {
                const int kh = t / 3, kw = t - kh * 3;
                const unsigned long long* wp =
                    (const unsigned long long*)(ws + t * 64 + to * 8);
                unsigned long long w0 = wp[0], w1 = wp[1], w2 = wp[2], w3 = wp[3];
                const int cb = tp + kw * d;
                const float2* brow0 = bs + kh * 144 + cb;
                const float2* brow1 = bs + (kh + 3) * 144 + cb;
                #pragma unroll
                for (int j = 0; j < 8; j++) {
                    const float2* src = (j < 4 ? brow0 : brow1) + 32 * (j & 3);
                    unsigned long long bv = *(const unsigned long long*)src;
                    FMA2(acc[0][j], w0, bv);
                    FMA2(acc[1][j], w1, bv);
                    FMA2(acc[2][j], w2, bv);
                    FMA2(acc[3][j], w3, bv);
                }
            }
        }
        __syncthreads();
    }
}

// ---------------------------------------------------------------------------
// Stage 3: per (b, dilation) dense conv Cin=192 -> Cout=64, write into g_cat
// ---------------------------------------------------------------------------
__global__ void __launch_bounds__(256, 2) branch_kernel()
{
    int blk = blockIdx.x;              // [0, 1024)
    int hp = blk & 63;
    int di = (blk >> 6) & 3;
    int b  = blk >> 8;
    int d  = 2 * di + 1;               // 1,3,5,7
    int h0 = hp * 2;

    unsigned long long acc[4][8];
    conv_tile2<NMC>(g_xm + b * NMC * HW, g_wbr + b * NMC * 576, d, h0, acc);

    int tp = threadIdx.x & 31, to = threadIdx.x >> 5;
    float* cb = g_cat + (b * NIC2 + di * 64) * HW;
    #pragma unroll
    for (int p = 0; p < 4; p++) {
        float* c0 = cb + (to * 8 + 2 * p) * HW;
        float* c1 = c0 + HW;
        #pragma unroll
        for (int j = 0; j < 8; j++) {
            float2 v = *(float2*)&acc[p][j];
            int w_ = tp + 32 * (j & 3);
            int h_ = h0 + (j >> 2);
            c0[h_ * 128 + w_] = v.x;
            c1[h_ * 128 + w_] = v.y;
        }
    }
}

// ---------------------------------------------------------------------------
// Stage 4: fuse conv Cin=256 -> Cout=64 (dil 1) + bias + BN(eval) + ReLU
// ---------------------------------------------------------------------------
__global__ void __launch_bounds__(256, 2) out_kernel(const float* __restrict__ cob,
                                                     const float* __restrict__ gamma,
                                                     const float* __restrict__ beta,
                                                     const float* __restrict__ mean,
                                                     const float* __restrict__ var,
                                                     float* __restrict__ out)
{
    int blk = blockIdx.x;              // [0, 256)
    int hp = blk & 63;
    int b  = blk >> 6;
    int h0 = hp * 2;

    unsigned long long acc[4][8];
    conv_tile2<NIC2>(g_cat + b * NIC2 * HW, g_wout, 1, h0, acc);

    int tp = threadIdx.x & 31, to = threadIdx.x >> 5;
    #pragma unroll
    for (int p = 0; p < 4; p++) {
        int o0 = to * 8 + 2 * p;
        int o1 = o0 + 1;
        float inv0  = gamma[o0] * rsqrtf(var[o0] + 1e-5f);
        float add0  = beta[o0] - mean[o0] * inv0;
        float bias0 = cob[o0];
        float inv1  = gamma[o1] * rsqrtf(var[o1] + 1e-5f);
        float add1  = beta[o1] - mean[o1] * inv1;
        float bias1 = cob[o1];
        float* p0 = out + (b * NO + o0) * HW;
        float* p1 = p0 + HW;
        #pragma unroll
        for (int j = 0; j < 8; j++) {
            float2 v = *(float2*)&acc[p][j];
            int w_ = tp + 32 * (j & 3);
            int h_ = h0 + (j >> 2);
            p0[h_ * 128 + w_] = fmaxf((v.x + bias0) * inv0 + add0, 0.f);
            p1[h_ * 128 + w_] = fmaxf((v.y + bias1) * inv1 + add1, 0.f);
        }
    }
}

// ---------------------------------------------------------------------------
extern "C" void kernel_launch(void* const* d_in, const int* in_sizes, int n_in,
                              void* d_out, int out_size)
{
    const float* x     = (const float*)d_in[0];
    const float* kern  = (const float*)d_in[1];
    const float* mw    = (const float*)d_in[2];
    const float* mb    = (const float*)d_in[3];
    const float* cow   = (const float*)d_in[4];
    const float* cob   = (const float*)d_in[5];
    const float* gamma = (const float*)d_in[6];
    const float* beta  = (const float*)d_in[7];
    const float* mean  = (const float*)d_in[8];
    const float* var   = (const float*)d_in[9];

    float* out   = (float*)d_out;
    float* masks = out + NB * NO * HW;   // tuple output: (out, masks)

    prep_w_kernel<<<1728, 256>>>(kern, cow);
    mask_kernel<<<NB * HW / 256, 256>>>(x, mw, mb, masks);
    xm_kernel<<<NB * NMC * HW / 256, 256>>>(x, masks);
    branch_kernel<<<NB * 4 * 64, 256>>>();
    out_kernel<<<NB * 64, 256>>>(cob, gamma, beta, mean, var, out);
}

// round 3
// speedup vs baseline: 1.1577x; 1.0899x over previous
#include <cuda_runtime.h>
#include <math.h>

// Problem constants
#define HH 128
#define WW 128
#define HW 16384        // 128*128
#define NB 4            // batch
#define NC 64           // in channels
#define NO 64           // out channels
#define NMC 192         // 3 masks * 64 channels
#define NIC2 256        // 4 dilations * 64

typedef unsigned long long ull;

// Scratch (device globals: allocation-free per harness rules)
__device__ float g_xm[NB * NMC * HW];        // 50.3 MB: x * mask, fused (m,c) channels
__device__ float g_cat[NB * NIC2 * HW];      // 67.1 MB: concatenated branch outputs
__device__ float g_wbr[NB * NMC * 9 * 64];   // packed branch weights [b][mc][tap][o]
__device__ float g_wout[NIC2 * 9 * 64];      // packed fuse weights  [ic][tap][o]

// Packed dual-fp32 FMA (sm_103a FFMA2; ptxas never auto-fuses this)
#define FMA2(acc, a, b) \
    asm("fma.rn.f32x2 %0, %1, %2, %0;" : "+l"(acc) : "l"(a), "l"(b))

// ---------------------------------------------------------------------------
// Weight prepack: branch weights kernel[b,m,o,c,kh,kw] -> [b][mc=m*64+c][tap][o]
//                 fuse weights conv_out_w[o,ic,kh,kw]  -> [ic][tap][o]
// ---------------------------------------------------------------------------
__global__ void prep_w_kernel(const float* __restrict__ kern,
                              const float* __restrict__ cow)
{
    int i = blockIdx.x * 256 + threadIdx.x;
    if (i < NB * NMC * 9 * 64) {
        int o   = i & 63;
        int rt  = i >> 6;        // r*9 + tap
        int tap = rt % 9;
        int r   = rt / 9;        // b*192 + mc
        int b   = r / NMC;
        int mc  = r - b * NMC;
        int m   = mc >> 6;
        int c   = mc & 63;
        g_wbr[i] = kern[(((b * 3 + m) * 64 + o) * 64 + c) * 9 + tap];
    }
    if (i < NIC2 * 9 * 64) {
        int o   = i & 63;
        int rt  = i >> 6;
        int tap = rt % 9;
        int ic  = rt / 9;
        g_wout[i] = cow[(o * NIC2 + ic) * 9 + tap];
    }
}

// ---------------------------------------------------------------------------
// Stage 1: mask conv (3x3, pad 1) + channel softmax over 3. One thread/pixel.
// ---------------------------------------------------------------------------
__global__ void mask_kernel(const float* __restrict__ x,
                            const float* __restrict__ mw,
                            const float* __restrict__ mb,
                            float* __restrict__ masks)
{
    __shared__ float s_mw[3 * 64 * 9];
    for (int i = threadIdx.x; i < 3 * 64 * 9; i += 256) s_mw[i] = mw[i];
    __syncthreads();

    int gid = blockIdx.x * 256 + threadIdx.x;   // < 65536
    int b   = gid >> 14;
    int pid = gid & (HW - 1);
    int h   = pid >> 7;
    int w   = pid & 127;

    float a0 = mb[0], a1 = mb[1], a2 = mb[2];
    const float* xb = x + b * NC * HW;
    for (int c = 0; c < NC; c++) {
        const float* xc = xb + c * HW;
        const float* wc = s_mw + c * 9;
        #pragma unroll
        for (int kh = 0; kh < 3; kh++) {
            int hh = h + kh - 1;
            if ((unsigned)hh >= 128u) continue;
            #pragma unroll
            for (int kw = 0; kw < 3; kw++) {
                int ww = w + kw - 1;
                if ((unsigned)ww >= 128u) continue;
                float v = xc[hh * 128 + ww];
                int t = kh * 3 + kw;
                a0 = fmaf(v, wc[t],            a0);
                a1 = fmaf(v, wc[64 * 9 + t],   a1);
                a2 = fmaf(v, wc[128 * 9 + t],  a2);
            }
        }
    }
    float mx = fmaxf(a0, fmaxf(a1, a2));
    float e0 = expf(a0 - mx), e1 = expf(a1 - mx), e2 = expf(a2 - mx);
    float inv = 1.f / (e0 + e1 + e2);
    masks[(b * 3 + 0) * HW + pid] = e0 * inv;
    masks[(b * 3 + 1) * HW + pid] = e1 * inv;
    masks[(b * 3 + 2) * HW + pid] = e2 * inv;
}

// ---------------------------------------------------------------------------
// Stage 2: xm[b][m*64+c][p] = x[b][c][p] * masks[b][m][p]
// ---------------------------------------------------------------------------
__global__ void xm_kernel(const float* __restrict__ x,
                          const float* __restrict__ masks)
{
    int i = blockIdx.x * 256 + threadIdx.x;     // < 4*192*16384
    int pid = i & (HW - 1);
    int r   = i >> 14;          // b*192 + mc
    int b   = r / NMC;
    int mc  = r - b * NMC;
    int m   = mc >> 6;
    int c   = mc & 63;
    g_xm[i] = x[(b * NC + c) * HW + pid] * masks[(b * 3 + m) * HW + pid];
}

// ---------------------------------------------------------------------------
// Core conv tile: block computes 64 out-ch x (2 rows x 128 cols).
// f32x2 accumulators pack the TWO OUTPUT ROWS (h0, h0+1) for one (o, col).
// B smem holds natural row-pair float2 (no duplication, 8B-aligned for any
// kw*d offset, 1 crossbar phase per value). Weights are duplicated float2,
// but weight loads are warp-uniform broadcasts (1 phase regardless).
// Per tap per warp: 8 bcast weight LDS.64 + 4 B LDS.64 = 12 phases / 32 FMA2.
// ---------------------------------------------------------------------------
template <int NIC>
__device__ __forceinline__ void conv_tile2(const float* __restrict__ xin,   // [NIC][HW]
                                           const float* __restrict__ wsrc,  // [NIC][9][64]
                                           int d, int h0,
                                           ull acc[8][4])
{
    __shared__ float2 Bs[2][3 * 144];   // [kh][col]: (row h0+(kh-1)d, +1) pairs
    __shared__ float2 Ws[2][9 * 64];    // duplicated weights (w, w)

    const int tid = threadIdx.x;
    const int tp = tid & 31, to = tid >> 5;
    const int Win = 128 + 2 * d;

    // Precompute this thread's B-fill slots (<=2): entry (r, c) with
    // r in 0..2 -> input rows h0+(r-1)*d and h0+1+(r-1)*d, col c-d.
    int loff0[2], loff1[2], lsm[2];
    int lcnt = 0;
    for (int idx = tid; idx < 3 * Win; idx += 256) {
        int r  = idx / Win;
        int cc = idx - r * Win;
        int win  = cc - d;
        int hin0 = h0 + (r - 1) * d;
        int hin1 = hin0 + 1;
        lsm[lcnt]   = r * 144 + cc;
        bool cok    = (unsigned)win < 128u;
        loff0[lcnt] = (cok && (unsigned)hin0 < 128u) ? (hin0 * 128 + win) : -1;
        loff1[lcnt] = (cok && (unsigned)hin1 < 128u) ? (hin1 * 128 + win) : -1;
        lcnt++;
    }

    #pragma unroll
    for (int i = 0; i < 8; i++)
        #pragma unroll
        for (int j = 0; j < 4; j++) acc[i][j] = 0ull;

    for (int mc0 = 0; mc0 < NIC; mc0 += 2) {
        #pragma unroll
        for (int s = 0; s < 2; s++) {
            const float* xc = xin + (mc0 + s) * HW;
            for (int l = 0; l < lcnt; l++) {
                float v0 = 0.f, v1 = 0.f;
                if (loff0[l] >= 0) v0 = __ldg(xc + loff0[l]);
                if (loff1[l] >= 0) v1 = __ldg(xc + loff1[l]);
                Bs[s][lsm[l]] = make_float2(v0, v1);
            }
            const float* wc = wsrc + (mc0 + s) * 576;
            #pragma unroll
            for (int i = tid; i < 576; i += 256) {
                float w = __ldg(wc + i);
                Ws[s][i] = make_float2(w, w);
            }
        }
        __syncthreads();

        #pragma unroll
        for (int s = 0; s < 2; s++) {
            const float2* ws = Ws[s];
            const float2* bs = Bs[s];
            #pragma unroll
            for (int t = 0; t < 9; t++) {
                const int kh = t / 3, kw = t - kh * 3;
                const ull* wp = (const ull*)(ws + t * 64 + to * 8);
                ull w0 = wp[0], w1 = wp[1], w2 = wp[2], w3 = wp[3];
                ull w4 = wp[4], w5 = wp[5], w6 = wp[6], w7 = wp[7];
                const ull* bp = (const ull*)(bs + kh * 144 + tp + kw * d);
                ull b0 = bp[0], b1 = bp[32], b2 = bp[64], b3 = bp[96];
                #pragma unroll
                for (int j = 0; j < 4; j++) {
                    ull bv = (j == 0) ? b0 : (j == 1) ? b1 : (j == 2) ? b2 : b3;
                    FMA2(acc[0][j], w0, bv);
                    FMA2(acc[1][j], w1, bv);
                    FMA2(acc[2][j], w2, bv);
                    FMA2(acc[3][j], w3, bv);
                    FMA2(acc[4][j], w4, bv);
                    FMA2(acc[5][j], w5, bv);
                    FMA2(acc[6][j], w6, bv);
                    FMA2(acc[7][j], w7, bv);
                }
            }
        }
        __syncthreads();
    }
}

// ---------------------------------------------------------------------------
// Stage 3: per (b, dilation) dense conv Cin=192 -> Cout=64, write into g_cat
// ---------------------------------------------------------------------------
__global__ void __launch_bounds__(256, 2) branch_kernel()
{
    int blk = blockIdx.x;              // [0, 1024)
    int hp = blk & 63;
    int di = (blk >> 6) & 3;
    int b  = blk >> 8;
    int d  = 2 * di + 1;               // 1,3,5,7
    int h0 = hp * 2;

    ull acc[8][4];
    conv_tile2<NMC>(g_xm + b * NMC * HW, g_wbr + b * NMC * 576, d, h0, acc);

    int tp = threadIdx.x & 31, to = threadIdx.x >> 5;
    float* cb = g_cat + (b * NIC2 + di * 64) * HW;
    #pragma unroll
    for (int i = 0; i < 8; i++) {
        float* cbo = cb + (to * 8 + i) * HW + h0 * 128;
        #pragma unroll
        for (int j = 0; j < 4; j++) {
            float2 v = *(float2*)&acc[i][j];
            int w_ = tp + 32 * j;
            cbo[w_]       = v.x;
            cbo[128 + w_] = v.y;
        }
    }
}

// ---------------------------------------------------------------------------
// Stage 4: fuse conv Cin=256 -> Cout=64 (dil 1) + bias + BN(eval) + ReLU
// ---------------------------------------------------------------------------
__global__ void __launch_bounds__(256, 2) out_kernel(const float* __restrict__ cob,
                                                     const float* __restrict__ gamma,
                                                     const float* __restrict__ beta,
                                                     const float* __restrict__ mean,
                                                     const float* __restrict__ var,
                                                     float* __restrict__ out)
{
    int blk = blockIdx.x;              // [0, 256)
    int hp = blk & 63;
    int b  = blk >> 6;
    int h0 = hp * 2;

    ull acc[8][4];
    conv_tile2<NIC2>(g_cat + b * NIC2 * HW, g_wout, 1, h0, acc);

    int tp = threadIdx.x & 31, to = threadIdx.x >> 5;
    #pragma unroll
    for (int i = 0; i < 8; i++) {
        int o = to * 8 + i;
        float inv  = gamma[o] * rsqrtf(var[o] + 1e-5f);
        float addv = beta[o] - mean[o] * inv;
        float bias = cob[o];
        float* po = out + (b * NO + o) * HW + h0 * 128;
        #pragma unroll
        for (int j = 0; j < 4; j++) {
            float2 v = *(float2*)&acc[i][j];
            int w_ = tp + 32 * j;
            po[w_]       = fmaxf((v.x + bias) * inv + addv, 0.f);
            po[128 + w_] = fmaxf((v.y + bias) * inv + addv, 0.f);
        }
    }
}

// ---------------------------------------------------------------------------
extern "C" void kernel_launch(void* const* d_in, const int* in_sizes, int n_in,
                              void* d_out, int out_size)
{
    const float* x     = (const float*)d_in[0];
    const float* kern  = (const float*)d_in[1];
    const float* mw    = (const float*)d_in[2];
    const float* mb    = (const float*)d_in[3];
    const float* cow   = (const float*)d_in[4];
    const float* cob   = (const float*)d_in[5];
    const float* gamma = (const float*)d_in[6];
    const float* beta  = (const float*)d_in[7];
    const float* mean  = (const float*)d_in[8];
    const float* var   = (const float*)d_in[9];

    float* out   = (float*)d_out;
    float* masks = out + NB * NO * HW;   // tuple output: (out, masks)

    prep_w_kernel<<<1728, 256>>>(kern, cow);
    mask_kernel<<<NB * HW / 256, 256>>>(x, mw, mb, masks);
    xm_kernel<<<NB * NMC * HW / 256, 256>>>(x, masks);
    branch_kernel<<<NB * 4 * 64, 256>>>();
    out_kernel<<<NB * 64, 256>>>(cob, gamma, beta, mean, var, out);
}

// round 4
// speedup vs baseline: 1.3326x; 1.1511x over previous
#include <cuda_runtime.h>
#include <math.h>

// Problem constants
#define HH 128
#define WW 128
#define HW 16384        // 128*128
#define NB 4            // batch
#define NC 64           // in channels
#define NO 64           // out channels
#define NMC 192         // 3 masks * 64 channels
#define NIC2 256        // 4 dilations * 64

typedef unsigned long long ull;

// Scratch (device globals: allocation-free per harness rules)
__device__ float g_xm[NB * NMC * HW];        // 50.3 MB: x * mask, fused (m,c) channels
__device__ float g_cat[NB * NIC2 * HW];      // 67.1 MB: concatenated branch outputs
__device__ float g_wbr[NB * NMC * 9 * 64];   // packed branch weights [b][mc][tap][o]
__device__ float g_wout[NIC2 * 9 * 64];      // packed fuse weights  [ic][tap][o]

// Packed dual-fp32 FMA (sm_103a FFMA2; ptxas never auto-fuses this)
#define FMA2(acc, a, b) \
    asm("fma.rn.f32x2 %0, %1, %2, %0;" : "+l"(acc) : "l"(a), "l"(b))

// 4-byte cp.async with zero-fill when sz==0 (OOB padding)
#define CP4(saddr, gptr, sz) \
    asm volatile("cp.async.ca.shared.global [%0], [%1], 4, %2;" \
                 :: "r"(saddr), "l"(gptr), "r"(sz))
#define CP_COMMIT() asm volatile("cp.async.commit_group;")
#define CP_WAIT0()  asm volatile("cp.async.wait_group 0;")

// ---------------------------------------------------------------------------
// Weight prepack: branch weights kernel[b,m,o,c,kh,kw] -> [b][mc=m*64+c][tap][o]
//                 fuse weights conv_out_w[o,ic,kh,kw]  -> [ic][tap][o]
// ---------------------------------------------------------------------------
__global__ void prep_w_kernel(const float* __restrict__ kern,
                              const float* __restrict__ cow)
{
    int i = blockIdx.x * 256 + threadIdx.x;
    if (i < NB * NMC * 9 * 64) {
        int o   = i & 63;
        int rt  = i >> 6;        // r*9 + tap
        int tap = rt % 9;
        int r   = rt / 9;        // b*192 + mc
        int b   = r / NMC;
        int mc  = r - b * NMC;
        int m   = mc >> 6;
        int c   = mc & 63;
        g_wbr[i] = kern[(((b * 3 + m) * 64 + o) * 64 + c) * 9 + tap];
    }
    if (i < NIC2 * 9 * 64) {
        int o   = i & 63;
        int rt  = i >> 6;
        int tap = rt % 9;
        int ic  = rt / 9;
        g_wout[i] = cow[(o * NIC2 + ic) * 9 + tap];
    }
}

// ---------------------------------------------------------------------------
// Stage 1: mask conv (3x3, pad 1) + channel softmax over 3. One thread/pixel.
// ---------------------------------------------------------------------------
__global__ void mask_kernel(const float* __restrict__ x,
                            const float* __restrict__ mw,
                            const float* __restrict__ mb,
                            float* __restrict__ masks)
{
    __shared__ float s_mw[3 * 64 * 9];
    for (int i = threadIdx.x; i < 3 * 64 * 9; i += 256) s_mw[i] = mw[i];
    __syncthreads();

    int gid = blockIdx.x * 256 + threadIdx.x;   // < 65536
    int b   = gid >> 14;
    int pid = gid & (HW - 1);
    int h   = pid >> 7;
    int w   = pid & 127;

    float a0 = mb[0], a1 = mb[1], a2 = mb[2];
    const float* xb = x + b * NC * HW;
    for (int c = 0; c < NC; c++) {
        const float* xc = xb + c * HW;
        const float* wc = s_mw + c * 9;
        #pragma unroll
        for (int kh = 0; kh < 3; kh++) {
            int hh = h + kh - 1;
            if ((unsigned)hh >= 128u) continue;
            #pragma unroll
            for (int kw = 0; kw < 3; kw++) {
                int ww = w + kw - 1;
                if ((unsigned)ww >= 128u) continue;
                float v = xc[hh * 128 + ww];
                int t = kh * 3 + kw;
                a0 = fmaf(v, wc[t],            a0);
                a1 = fmaf(v, wc[64 * 9 + t],   a1);
                a2 = fmaf(v, wc[128 * 9 + t],  a2);
            }
        }
    }
    float mx = fmaxf(a0, fmaxf(a1, a2));
    float e0 = expf(a0 - mx), e1 = expf(a1 - mx), e2 = expf(a2 - mx);
    float inv = 1.f / (e0 + e1 + e2);
    masks[(b * 3 + 0) * HW + pid] = e0 * inv;
    masks[(b * 3 + 1) * HW + pid] = e1 * inv;
    masks[(b * 3 + 2) * HW + pid] = e2 * inv;
}

// ---------------------------------------------------------------------------
// Stage 2: xm[b][m*64+c][p] = x[b][c][p] * masks[b][m][p]
// ---------------------------------------------------------------------------
__global__ void xm_kernel(const float* __restrict__ x,
                          const float* __restrict__ masks)
{
    int i = blockIdx.x * 256 + threadIdx.x;     // < 4*192*16384
    int pid = i & (HW - 1);
    int r   = i >> 14;          // b*192 + mc
    int b   = r / NMC;
    int mc  = r - b * NMC;
    int m   = mc >> 6;
    int c   = mc & 63;
    g_xm[i] = x[(b * NC + c) * HW + pid] * masks[(b * 3 + m) * HW + pid];
}

// ---------------------------------------------------------------------------
// Core conv tile: block computes 64 out-ch x (2 rows x 128 cols).
// f32x2 accumulators pack the TWO OUTPUT ROWS (h0, h0+1).
// Double-buffered smem; B filled via 4B cp.async (zfill OOB), weights
// prefetched to regs and stored duplicated. One barrier per channel-pair;
// all fill latency overlapped with math.
// ---------------------------------------------------------------------------
#define BS_STRIDE (2 * 3 * 144)     // one buffer of B (ull units)
#define WS_STRIDE (2 * 576)         // one buffer of W (float2 units)
#define NWPF 5                      // weight prefetch slots: ceil(1152/256)

template <int NIC>
__device__ __forceinline__ void conv_tile2(const float* __restrict__ xin,   // [NIC][HW]
                                           const float* __restrict__ wsrc,  // [NIC][9][64]
                                           int d, int h0,
                                           ull acc[8][4])
{
    __shared__ float2 Bs[2 * BS_STRIDE];   // [buf][ch][kh][col] row-pairs
    __shared__ float2 Ws[2 * WS_STRIDE];   // [buf][ch][tap*64+o] dup weights

    const int tid = threadIdx.x;
    const int tp = tid & 31, to = tid >> 5;
    const int Win = 128 + 2 * d;

    // This thread's B-fill slots (<=2) and smem byte addresses
    unsigned bs_base = (unsigned)__cvta_generic_to_shared(Bs);
    int lcnt = 0;
    int loff0[2], loff1[2];
    unsigned sadr[2];
    for (int idx = tid; idx < 3 * Win; idx += 256) {
        int r  = idx / Win;
        int cc = idx - r * Win;
        int win  = cc - d;
        int hin0 = h0 + (r - 1) * d;
        int hin1 = hin0 + 1;
        bool cok = (unsigned)win < 128u;
        loff0[lcnt] = (cok && (unsigned)hin0 < 128u) ? (hin0 * 128 + win) : -1;
        loff1[lcnt] = (cok && (unsigned)hin1 < 128u) ? (hin1 * 128 + win) : -1;
        sadr[lcnt]  = bs_base + (unsigned)(r * 144 + cc) * 8u;
        lcnt++;
    }

    // This thread's weight prefetch indices over flat [2ch][576]
    int wof[NWPF];    // gmem offset within pair: s*576*... -> (s, idx)
    int wsm[NWPF];    // smem float2 index within buffer
    #pragma unroll
    for (int l = 0; l < NWPF; l++) {
        int f = tid + 256 * l;
        if (f < 1152) {
            int s   = f >= 576;
            int idx = f - s * 576;
            wof[l] = s * 576 + idx;   // == f, but keep explicit
            wsm[l] = s * 576 + idx;
        } else { wof[l] = -1; wsm[l] = 0; }
    }

    #pragma unroll
    for (int i = 0; i < 8; i++)
        #pragma unroll
        for (int j = 0; j < 4; j++) acc[i][j] = 0ull;

    float wreg[NWPF];

    // ---- prologue: fill buffer 0 with pair 0 ----
    {
        #pragma unroll
        for (int s = 0; s < 2; s++) {
            const float* xc = xin + s * HW;
            unsigned so = (unsigned)(s * 3 * 144) * 8u;
            for (int l = 0; l < lcnt; l++) {
                const float* p0 = (loff0[l] >= 0) ? xc + loff0[l] : xc;
                const float* p1 = (loff1[l] >= 0) ? xc + loff1[l] : xc;
                CP4(sadr[l] + so,      p0, (loff0[l] >= 0) ? 4 : 0);
                CP4(sadr[l] + so + 4,  p1, (loff1[l] >= 0) ? 4 : 0);
            }
        }
        CP_COMMIT();
        #pragma unroll
        for (int l = 0; l < NWPF; l++)
            if (wof[l] >= 0) wreg[l] = __ldg(wsrc + wof[l]);
        CP_WAIT0();
        #pragma unroll
        for (int l = 0; l < NWPF; l++)
            if (wof[l] >= 0) Ws[wsm[l]] = make_float2(wreg[l], wreg[l]);
    }
    __syncthreads();

    const int NPAIR = NIC / 2;
    for (int k = 0; k < NPAIR; k++) {
        const int cur = k & 1, nxt = cur ^ 1;
        const int mc2 = 2 * (k + 1);
        const bool more = (k + 1) < NPAIR;

        // issue next pair's B fills + weight LDGs (overlap with math)
        if (more) {
            unsigned bufo = (unsigned)(nxt * BS_STRIDE) * 8u;
            #pragma unroll
            for (int s = 0; s < 2; s++) {
                const float* xc = xin + (mc2 + s) * HW;
                unsigned so = bufo + (unsigned)(s * 3 * 144) * 8u;
                for (int l = 0; l < lcnt; l++) {
                    const float* p0 = (loff0[l] >= 0) ? xc + loff0[l] : xc;
                    const float* p1 = (loff1[l] >= 0) ? xc + loff1[l] : xc;
                    CP4(sadr[l] + so,     p0, (loff0[l] >= 0) ? 4 : 0);
                    CP4(sadr[l] + so + 4, p1, (loff1[l] >= 0) ? 4 : 0);
                }
            }
            const float* wp = wsrc + mc2 * 576;
            #pragma unroll
            for (int l = 0; l < NWPF; l++)
                if (wof[l] >= 0) wreg[l] = __ldg(wp + wof[l]);
        }
        CP_COMMIT();

        // ---- math on current buffer ----
        const float2* bsb = Bs + cur * BS_STRIDE;
        const float2* wsb = Ws + cur * WS_STRIDE;
        #pragma unroll
        for (int s = 0; s < 2; s++) {
            const float2* ws = wsb + s * 576;
            const float2* bs = bsb + s * 3 * 144;
            #pragma unroll
            for (int t = 0; t < 9; t++) {
                const int kh = t / 3, kw = t - kh * 3;
                const ull* wp = (const ull*)(ws + t * 64 + to * 8);
                ull w0 = wp[0], w1 = wp[1], w2 = wp[2], w3 = wp[3];
                ull w4 = wp[4], w5 = wp[5], w6 = wp[6], w7 = wp[7];
                const ull* bp = (const ull*)(bs + kh * 144 + tp + kw * d);
                ull b0 = bp[0], b1 = bp[32], b2 = bp[64], b3 = bp[96];
                #pragma unroll
                for (int j = 0; j < 4; j++) {
                    ull bv = (j == 0) ? b0 : (j == 1) ? b1 : (j == 2) ? b2 : b3;
                    FMA2(acc[0][j], w0, bv);
                    FMA2(acc[1][j], w1, bv);
                    FMA2(acc[2][j], w2, bv);
                    FMA2(acc[3][j], w3, bv);
                    FMA2(acc[4][j], w4, bv);
                    FMA2(acc[5][j], w5, bv);
                    FMA2(acc[6][j], w6, bv);
                    FMA2(acc[7][j], w7, bv);
                }
            }
        }

        CP_WAIT0();
        if (more) {
            float2* wd = Ws + nxt * WS_STRIDE;
            #pragma unroll
            for (int l = 0; l < NWPF; l++)
                if (wof[l] >= 0) wd[wsm[l]] = make_float2(wreg[l], wreg[l]);
        }
        __syncthreads();
    }
}

// ---------------------------------------------------------------------------
// Stage 3: per (b, dilation) dense conv Cin=192 -> Cout=64, write into g_cat
// ---------------------------------------------------------------------------
__global__ void __launch_bounds__(256, 2) branch_kernel()
{
    int blk = blockIdx.x;              // [0, 1024)
    int hp = blk & 63;
    int di = (blk >> 6) & 3;
    int b  = blk >> 8;
    int d  = 2 * di + 1;               // 1,3,5,7
    int h0 = hp * 2;

    ull acc[8][4];
    conv_tile2<NMC>(g_xm + b * NMC * HW, g_wbr + b * NMC * 576, d, h0, acc);

    int tp = threadIdx.x & 31, to = threadIdx.x >> 5;
    float* cb = g_cat + (b * NIC2 + di * 64) * HW;
    #pragma unroll
    for (int i = 0; i < 8; i++) {
        float* cbo = cb + (to * 8 + i) * HW + h0 * 128;
        #pragma unroll
        for (int j = 0; j < 4; j++) {
            float2 v = *(float2*)&acc[i][j];
            int w_ = tp + 32 * j;
            cbo[w_]       = v.x;
            cbo[128 + w_] = v.y;
        }
    }
}

// ---------------------------------------------------------------------------
// Stage 4: fuse conv Cin=256 -> Cout=64 (dil 1) + bias + BN(eval) + ReLU
// ---------------------------------------------------------------------------
__global__ void __launch_bounds__(256, 2) out_kernel(const float* __restrict__ cob,
                                                     const float* __restrict__ gamma,
                                                     const float* __restrict__ beta,
                                                     const float* __restrict__ mean,
                                                     const float* __restrict__ var,
                                                     float* __restrict__ out)
{
    int blk = blockIdx.x;              // [0, 256)
    int hp = blk & 63;
    int b  = blk >> 6;
    int h0 = hp * 2;

    ull acc[8][4];
    conv_tile2<NIC2>(g_cat + b * NIC2 * HW, g_wout, 1, h0, acc);

    int tp = threadIdx.x & 31, to = threadIdx.x >> 5;
    #pragma unroll
    for (int i = 0; i < 8; i++) {
        int o = to * 8 + i;
        float inv  = gamma[o] * rsqrtf(var[o] + 1e-5f);
        float addv = beta[o] - mean[o] * inv;
        float bias = cob[o];
        float* po = out + (b * NO + o) * HW + h0 * 128;
        #pragma unroll
        for (int j = 0; j < 4; j++) {
            float2 v = *(float2*)&acc[i][j];
            int w_ = tp + 32 * j;
            po[w_]       = fmaxf((v.x + bias) * inv + addv, 0.f);
            po[128 + w_] = fmaxf((v.y + bias) * inv + addv, 0.f);
        }
    }
}

// ---------------------------------------------------------------------------
extern "C" void kernel_launch(void* const* d_in, const int* in_sizes, int n_in,
                              void* d_out, int out_size)
{
    const float* x     = (const float*)d_in[0];
    const float* kern  = (const float*)d_in[1];
    const float* mw    = (const float*)d_in[2];
    const float* mb    = (const float*)d_in[3];
    const float* cow   = (const float*)d_in[4];
    const float* cob   = (const float*)d_in[5];
    const float* gamma = (const float*)d_in[6];
    const float* beta  = (const float*)d_in[7];
    const float* mean  = (const float*)d_in[8];
    const float* var   = (const float*)d_in[9];

    float* out   = (float*)d_out;
    float* masks = out + NB * NO * HW;   // tuple output: (out, masks)

    prep_w_kernel<<<1728, 256>>>(kern, cow);
    mask_kernel<<<NB * HW / 256, 256>>>(x, mw, mb, masks);
    xm_kernel<<<NB * NMC * HW / 256, 256>>>(x, masks);
    branch_kernel<<<NB * 4 * 64, 256>>>();
    out_kernel<<<NB * 64, 256>>>(cob, gamma, beta, mean, var, out);
}